// round 15
// baseline (speedup 1.0000x reference)
#include <cuda_runtime.h>
#include <cuda_fp16.h>
#include <cstdint>

#define NG 50000
#define NP 20000
#define NV 10000
#define NT 80000
#define HID 128
#define EPER 250000
#define CDIV(a,b) (((a)+(b)-1)/(b))

#define OFF_TG 0
#define OFF_IN (NG)
#define OFF_CT (NG+NP)
#define OFF_II (2*NG+NP)
#define CNTS_SZ (3*NG+NP)
#define CURZ_SZ (3*NG+NP+NT)

#define RB0 0
#define RB1 (EPER + 3*NG)
#define RB2 (RB1 + EPER + 3*NP)
#define RB3 (RB2 + EPER + 3*NG)
#define RSRC_SZ (RB3 + EPER + 3*NG)
#define CSRC_SZ (4*EPER + 4*NT)

// ------------------------- device scratch -------------------------
__device__ float g_h0[NT*HID];
__device__ __align__(16) __half g_h16[(NT+1)*HID];
__device__ __align__(16) __half g_z16a[(NT+1)*HID];
__device__ __align__(16) __half g_z16b[(NT+1)*HID];
__device__ __align__(16) __half g_hq[NT*HID];
__device__ __align__(16) __half g_sg16[NG*512];
__device__ __align__(16) __half g_sp16[NP*256];
__device__ __align__(16) __half g_wtin16[(256+128+64)*HID];
__device__ __align__(16) __half g_wtg16[512*HID];
__device__ __align__(16) __half g_wtp16[256*HID];
__device__ float g_bg[HID];
__device__ int   g_degi[NT];
__device__ float g_dinv[NT];
__device__ int   g_off[NT+1];
__device__ int   g_cnts[CNTS_SZ];
__device__ int   g_curz[CURZ_SZ];
__device__ __align__(16) int g_csrc[CSRC_SZ];
__device__ int   g_roff_tg[NG+1];
__device__ int   g_roff_in[NP+1];
__device__ int   g_roff_ct[NG+1];
__device__ int   g_roff_ii[NG+1];
__device__ __align__(16) int g_rsrc[RSRC_SZ];

__device__ __forceinline__ uint32_t h2u(__half2 h) {
    uint32_t u;
    memcpy(&u, &h, 4);
    return u;
}

// ------------------------- setup kernels -------------------------
__global__ void k_hist4(const int* __restrict__ e0, const int* __restrict__ e1,
                        const int* __restrict__ e2, const int* __restrict__ e3) {
    int t = blockIdx.x * blockDim.x + threadIdx.x;
    if (t >= 4 * EPER) return;
    int r = t / EPER, e = t - r * EPER;
    const int* ei = (r == 0) ? e0 : (r == 1) ? e1 : (r == 2) ? e2 : e3;
    int base = (r == 0) ? OFF_TG : (r == 1) ? OFF_IN : (r == 2) ? OFF_CT : OFF_II;
    atomicAdd(&g_cnts[base + ei[EPER + e]], 1);
}

__global__ void k_deg() {
    int i = blockIdx.x * blockDim.x + threadIdx.x;
    if (i >= NT) return;
    int d = 1;
    if (i < NG) d += g_cnts[OFF_TG + i] + g_cnts[OFF_CT + i] + g_cnts[OFF_II + i];
    else if (i < NG + NP) d += g_cnts[OFF_IN + (i - NG)];
    g_degi[i] = d;
    g_dinv[i] = rsqrtf((float)d);
}

__global__ void k_scan5() {
    __shared__ int part[1024];
    const int* cnt; int* off; int n;
    switch (blockIdx.x) {
        case 0: cnt = g_cnts + OFF_TG; off = g_roff_tg; n = NG; break;
        case 1: cnt = g_cnts + OFF_IN; off = g_roff_in; n = NP; break;
        case 2: cnt = g_cnts + OFF_CT; off = g_roff_ct; n = NG; break;
        case 3: cnt = g_cnts + OFF_II; off = g_roff_ii; n = NG; break;
        default: cnt = g_degi; off = g_off; n = NT; break;
    }
    int t = threadIdx.x;
    int chunk = (n + 1023) / 1024;
    int lo = t * chunk, hi = min(lo + chunk, n);
    int s = 0;
    for (int i = lo; i < hi; i++) s += (cnt[i] + 3) & ~3;
    part[t] = s;
    __syncthreads();
    for (int o = 1; o < 1024; o <<= 1) {
        int x = (t >= o) ? part[t - o] : 0;
        __syncthreads();
        part[t] += x;
        __syncthreads();
    }
    int run = part[t] - s;
    for (int i = lo; i < hi; i++) { off[i] = run; run += (cnt[i] + 3) & ~3; }
    if (t == 1023) off[n] = part[1023];
}

__global__ void k_scatter_all(const int* __restrict__ e0, const int* __restrict__ e1,
                              const int* __restrict__ e2, const int* __restrict__ e3) {
    int t = blockIdx.x * blockDim.x + threadIdx.x;
    if (t < 4 * EPER) {
        int r = t / EPER, e = t - r * EPER;
        const int* ei; const int* roff; int cbase, osrc, odst, rb;
        if (r == 0)      { ei = e0; roff = g_roff_tg; cbase = OFF_TG; osrc = NG + NP; odst = 0;  rb = RB0; }
        else if (r == 1) { ei = e1; roff = g_roff_in; cbase = OFF_IN; osrc = 0;       odst = NG; rb = RB1; }
        else if (r == 2) { ei = e2; roff = g_roff_ct; cbase = OFF_CT; osrc = NG;      odst = 0;  rb = RB2; }
        else             { ei = e3; roff = g_roff_ii; cbase = OFF_II; osrc = 0;       odst = 0;  rb = RB3; }
        int s = ei[e], d = ei[EPER + e];
        int gs = s + osrc;
        int p = roff[d] + atomicAdd(&g_curz[cbase + d], 1);
        g_rsrc[rb + p] = gs;
        int gd = d + odst;
        int p2 = g_off[gd] + atomicAdd(&g_curz[CNTS_SZ + gd], 1);
        g_csrc[p2] = gs;
    } else if (t < 4 * EPER + NT) {
        int i = t - 4 * EPER;
        int p = g_off[i] + atomicAdd(&g_curz[CNTS_SZ + i], 1);
        g_csrc[p] = i;
    }
}

__global__ void k_padfill() {
    int i = blockIdx.x * blockDim.x + threadIdx.x;
    if (i >= 3 * NG + NP + NT) return;
    const int* offp; int node, real; int* arr; int rb;
    if (i < NG)               { node = i;                 offp = g_roff_tg; real = g_cnts[OFF_TG + node]; arr = g_rsrc; rb = RB0; }
    else if (i < NG + NP)     { node = i - NG;            offp = g_roff_in; real = g_cnts[OFF_IN + node]; arr = g_rsrc; rb = RB1; }
    else if (i < 2 * NG + NP) { node = i - (NG + NP);     offp = g_roff_ct; real = g_cnts[OFF_CT + node]; arr = g_rsrc; rb = RB2; }
    else if (i < 3 * NG + NP) { node = i - (2 * NG + NP); offp = g_roff_ii; real = g_cnts[OFF_II + node]; arr = g_rsrc; rb = RB3; }
    else                      { node = i - (3 * NG + NP); offp = g_off;     real = g_degi[node];          arr = g_csrc; rb = 0;   }
    int o = rb + offp[node];
    int pad = (real + 3) & ~3;
    for (int j = real; j < pad; j++) arr[o + j] = NT;
}

__global__ void k_prep16(const float* __restrict__ wg, const float* __restrict__ wp,
                         const float* __restrict__ wv, const float* __restrict__ wsl,
                         const float* __restrict__ wsr, const float* __restrict__ bsl,
                         int l, int do_in) {
    int idx = blockIdx.x * blockDim.x + threadIdx.x;
    const int TIN = (256 + 128 + 64) * 128;
    const int WG  = 512 * 128;
    int base = do_in ? TIN : 0;
    if (do_in && idx < TIN) {
        float v;
        if (idx < 256 * 128) v = wg[idx];
        else if (idx < (256 + 128) * 128) v = wp[idx - 256 * 128];
        else v = wv[idx - (256 + 128) * 128];
        g_wtin16[idx] = __float2half(v);
        return;
    }
    int i = idx - base;
    if (i < 0) return;
    if (i < WG) {
        int n = i >> 9, k = i & 511;
        int b = k >> 7, kk = k & 127;
        float v;
        if (b == 0)      v = wsl[((l * 4 + 0) * 128 + n) * 128 + kk];
        else if (b == 1) v = wsl[((l * 4 + 2) * 128 + n) * 128 + kk];
        else if (b == 2) v = wsl[((l * 4 + 3) * 128 + n) * 128 + kk];
        else             v = wsr[((l * 4 + 0) * 128 + n) * 128 + kk]
                           + wsr[((l * 4 + 2) * 128 + n) * 128 + kk]
                           + wsr[((l * 4 + 3) * 128 + n) * 128 + kk];
        g_wtg16[i] = __float2half(v);
        if (i < 128)
            g_bg[i] = bsl[(l * 4 + 0) * 128 + i] + bsl[(l * 4 + 2) * 128 + i]
                    + bsl[(l * 4 + 3) * 128 + i];
    } else if (i < WG + 256 * 128) {
        int j = i - WG;
        int n = j >> 8, k = j & 255;
        int b = k >> 7, kk = k & 127;
        float v = (b == 0) ? wsl[((l * 4 + 1) * 128 + n) * 128 + kk]
                           : wsr[((l * 4 + 1) * 128 + n) * 128 + kk];
        g_wtp16[j] = __float2half(v);
    }
}

// ------------------------- FP16 tensor-core GEMM (KTILE=32) -------------------------
__device__ __forceinline__ void mma_f16(float c[4], uint32_t a0, uint32_t a1,
                                        uint32_t a2, uint32_t a3,
                                        uint32_t b0, uint32_t b1) {
    asm volatile(
        "mma.sync.aligned.m16n8k16.row.col.f32.f16.f16.f32 "
        "{%0,%1,%2,%3}, {%4,%5,%6,%7}, {%8,%9}, {%0,%1,%2,%3};"
        : "+f"(c[0]), "+f"(c[1]), "+f"(c[2]), "+f"(c[3])
        : "r"(a0), "r"(a1), "r"(a2), "r"(a3), "r"(b0), "r"(b1));
}

#define SST 20
#define TBUF (128*SST)
#define GSMEM_BYTES (4*TBUF*4)

template<bool RES, bool AH>
__global__ __launch_bounds__(256)
void k_gemm16(const void* __restrict__ Araw, const __half* __restrict__ W16,
              const float* __restrict__ bias, const float* __restrict__ res,
              float* __restrict__ out, __half* __restrict__ h16out,
              __half* __restrict__ zs, __half* __restrict__ hqo,
              const float* __restrict__ dv,
              int M, int K, float scale)
{
    extern __shared__ uint32_t sm[];
    uint32_t* Asm = sm;
    uint32_t* Bsm = sm + 2 * TBUF;

    int tid  = threadIdx.x;
    int lane = tid & 31;
    int wid  = tid >> 5;
    int wm = wid >> 2;
    int wn = wid & 3;
    int g   = lane >> 2;
    int tig = lane & 3;

    int rowBase = blockIdx.x * 128;
    int r_ld  = tid >> 1;
    int hsel  = (tid & 1);

    float acc[4][4][4];
#pragma unroll
    for (int mt = 0; mt < 4; mt++)
#pragma unroll
        for (int nt = 0; nt < 4; nt++)
#pragma unroll
            for (int r = 0; r < 4; r++) acc[mt][nt][r] = 0.f;

    int ntk = K >> 5;
    int gr = rowBase + r_ld;
    const __half* Ah = (const __half*)Araw;
    const float*  Af = (const float*)Araw;

    auto loadA = [&](int k0, uint4& u0, uint4& u1) {
        if (AH) {
            if (gr < M) {
                const uint4* p = (const uint4*)&Ah[(size_t)gr * K + k0 + hsel * 16];
                u0 = p[0]; u1 = p[1];
            } else { u0 = make_uint4(0,0,0,0); u1 = make_uint4(0,0,0,0); }
        } else {
            if (gr < M) {
                const float4* p = (const float4*)&Af[(size_t)gr * K + k0 + hsel * 16];
                float4 f0 = p[0], f1 = p[1], f2 = p[2], f3 = p[3];
                uint32_t* w0 = (uint32_t*)&u0;
                uint32_t* w1 = (uint32_t*)&u1;
                w0[0] = h2u(__floats2half2_rn(f0.x, f0.y));
                w0[1] = h2u(__floats2half2_rn(f0.z, f0.w));
                w0[2] = h2u(__floats2half2_rn(f1.x, f1.y));
                w0[3] = h2u(__floats2half2_rn(f1.z, f1.w));
                w1[0] = h2u(__floats2half2_rn(f2.x, f2.y));
                w1[1] = h2u(__floats2half2_rn(f2.z, f2.w));
                w1[2] = h2u(__floats2half2_rn(f3.x, f3.y));
                w1[3] = h2u(__floats2half2_rn(f3.z, f3.w));
            } else { u0 = make_uint4(0,0,0,0); u1 = make_uint4(0,0,0,0); }
        }
    };
    auto loadB = [&](int k0, uint4& u0, uint4& u1) {
        const uint4* p = (const uint4*)&W16[(size_t)r_ld * K + k0 + hsel * 16];
        u0 = p[0]; u1 = p[1];
    };
    auto store = [&](uint32_t* buf, uint4 u0, uint4 u1) {
        int base = r_ld * SST + hsel * 8;
        *(uint4*)&buf[base] = u0;
        *(uint4*)&buf[base + 4] = u1;
    };

    {
        uint4 a0, a1, b0, b1;
        loadA(0, a0, a1);
        loadB(0, b0, b1);
        store(Asm, a0, a1);
        store(Bsm, b0, b1);
    }
    __syncthreads();

    for (int t = 0; t < ntk; t++) {
        int buf = t & 1;
        bool more = (t + 1 < ntk);
        uint4 an0, an1, bn0, bn1;
        if (more) {
            int k0 = (t + 1) << 5;
            loadA(k0, an0, an1);
            loadB(k0, bn0, bn1);
        }
        const uint32_t* Ab = Asm + buf * TBUF;
        const uint32_t* Bb = Bsm + buf * TBUF;
#pragma unroll
        for (int ks2 = 0; ks2 < 16; ks2 += 8) {
            uint32_t af[4][4], bf[4][2];
#pragma unroll
            for (int mt = 0; mt < 4; mt++) {
                int r0 = wm * 64 + mt * 16 + g;
                af[mt][0] = Ab[r0 * SST + ks2 + tig];
                af[mt][1] = Ab[(r0 + 8) * SST + ks2 + tig];
                af[mt][2] = Ab[r0 * SST + ks2 + tig + 4];
                af[mt][3] = Ab[(r0 + 8) * SST + ks2 + tig + 4];
            }
#pragma unroll
            for (int nt = 0; nt < 4; nt++) {
                int c0 = wn * 32 + nt * 8 + g;
                bf[nt][0] = Bb[c0 * SST + ks2 + tig];
                bf[nt][1] = Bb[c0 * SST + ks2 + tig + 4];
            }
#pragma unroll
            for (int mt = 0; mt < 4; mt++)
#pragma unroll
                for (int nt = 0; nt < 4; nt++)
                    mma_f16(acc[mt][nt], af[mt][0], af[mt][1], af[mt][2], af[mt][3],
                            bf[nt][0], bf[nt][1]);
        }
        if (more) {
            int nb = buf ^ 1;
            store(Asm + nb * TBUF, an0, an1);
            store(Bsm + nb * TBUF, bn0, bn1);
        }
        __syncthreads();
    }

#pragma unroll
    for (int mt = 0; mt < 4; mt++) {
#pragma unroll
        for (int nt = 0; nt < 4; nt++) {
            int col = wn * 32 + nt * 8 + tig * 2;
            float b0 = bias[col], b1 = bias[col + 1];
#pragma unroll
            for (int h = 0; h < 2; h++) {
                int row = rowBase + wm * 64 + mt * 16 + g + h * 8;
                if (row >= M) continue;
                float v0 = acc[mt][nt][h * 2 + 0] + b0;
                float v1 = acc[mt][nt][h * 2 + 1] + b1;
                if (RES) {
                    float2 rv = *(const float2*)&res[(size_t)row * HID + col];
                    v0 = rv.x + v0 * scale;
                    v1 = rv.y + v1 * scale;
                }
                v0 = fmaxf(v0, 0.f);
                v1 = fmaxf(v1, 0.f);
                float2 o; o.x = v0; o.y = v1;
                *(float2*)&out[(size_t)row * HID + col] = o;
                *(__half2*)&h16out[(size_t)row * HID + col] = __floats2half2_rn(v0, v1);
                if (zs) {
                    float d = dv[row];
                    *(__half2*)&zs[(size_t)row * HID + col] =
                        __floats2half2_rn(v0 * d, v1 * d);
                    *(__half2*)&hqo[(size_t)row * HID + col] =
                        __floats2half2_rn(0.1f * d * v0, 0.1f * d * v1);
                }
            }
        }
    }
}

// ------------------------- fp16 helpers -------------------------
__device__ __forceinline__ void h8_add(uint4 v, float a[8]) {
    const __half2* h = (const __half2*)&v;
#pragma unroll
    for (int j = 0; j < 4; j++) {
        float2 f = __half22float2(h[j]);
        a[2 * j]     += f.x;
        a[2 * j + 1] += f.y;
    }
}
__device__ __forceinline__ uint4 pack8(const float r[8]) {
    uint4 pk;
    __half2* ph = (__half2*)&pk;
    ph[0] = __floats2half2_rn(r[0], r[1]);
    ph[1] = __floats2half2_rn(r[2], r[3]);
    ph[2] = __floats2half2_rn(r[4], r[5]);
    ph[3] = __floats2half2_rn(r[6], r[7]);
    return pk;
}
// predicated gather load: pads (index NT) skip the memory transaction
__device__ __forceinline__ uint4 ld_row(const uint4* base, int s, int lane) {
    return (s < NT) ? __ldg(&base[(size_t)s * 16 + lane]) : make_uint4(0, 0, 0, 0);
}

// gather core: 16 lanes/node, padded CSR, mean into dst (fp16), optional row copy
__device__ __forceinline__ void gather_node(int node, const int* offp, const int* es,
                                            int real, __half* dst, int strideH, int colH,
                                            const __half* cp, int ccolH, int lane) {
    const uint4* x4 = (const uint4*)g_h16;
    int e0 = offp[node], e1 = offp[node + 1];
    float a[8] = {0.f, 0.f, 0.f, 0.f, 0.f, 0.f, 0.f, 0.f};
    for (int e = e0; e < e1; e += 4) {
        int4 s4 = *(const int4*)&es[e];
        uint4 v0 = ld_row(x4, s4.x, lane);
        uint4 v1 = ld_row(x4, s4.y, lane);
        uint4 v2 = ld_row(x4, s4.z, lane);
        uint4 v3 = ld_row(x4, s4.w, lane);
        h8_add(v0, a); h8_add(v1, a); h8_add(v2, a); h8_add(v3, a);
    }
    float inv = 1.f / fmaxf((float)real, 1.f);
    float r[8];
#pragma unroll
    for (int j = 0; j < 8; j++) r[j] = a[j] * inv;
    *(uint4*)&dst[(size_t)node * strideH + colH + lane * 8] = pack8(r);
    if (cp)
        *(uint4*)&dst[(size_t)node * strideH + ccolH + lane * 8] =
            ((const uint4*)cp)[(size_t)node * 16 + lane];
}

// gather A: ii (sg col 256) + copy hg (col 384); in (sp col 0) + copy hp (col 128)
__global__ void k_gather_A() {
    int t = blockIdx.x * blockDim.x + threadIdx.x;
    int lane = t & 15, slot = t >> 4;
    if (slot >= NG + NP) return;
    if (slot < NG) {
        gather_node(slot, g_roff_ii, g_rsrc + RB3, g_cnts[OFF_II + slot],
                    g_sg16, 512, 256, g_h16, 384, lane);
    } else {
        int node = slot - NG;
        gather_node(node, g_roff_in, g_rsrc + RB1, g_cnts[OFF_IN + node],
                    g_sp16, 256, 0, g_h16 + (size_t)NG * HID, 128, lane);
    }
}

// gather B: optional tg (sg col 0) + ct (sg col 128)
__global__ void k_gather_B(int do_tg) {
    int t = blockIdx.x * blockDim.x + threadIdx.x;
    int lane = t & 15, slot = t >> 4;
    int n_slots = do_tg ? 2 * NG : NG;
    if (slot >= n_slots) return;
    if (do_tg && slot < NG) {
        gather_node(slot, g_roff_tg, g_rsrc + RB0, g_cnts[OFF_TG + slot],
                    g_sg16, 512, 0, (const __half*)0, 0, lane);
    } else {
        int node = do_tg ? slot - NG : slot;
        gather_node(node, g_roff_ct, g_rsrc + RB2, g_cnts[OFF_CT + node],
                    g_sg16, 512, 128, (const __half*)0, 0, lane);
    }
}

// ------------------------- APPNP step (padded CSR, 16 lanes/node, pad-skip) -------------------------
template<bool LAST>
__global__ void k_appnp_s(const uint4* __restrict__ z, uint4* __restrict__ zn,
                          float4* __restrict__ outf) {
    int t = blockIdx.x * blockDim.x + threadIdx.x;
    int lane = t & 15, node = t >> 4;
    if (node >= NT) return;
    int e0 = g_off[node], e1 = g_off[node + 1];
    float a[8] = {0.f, 0.f, 0.f, 0.f, 0.f, 0.f, 0.f, 0.f};
    for (int e = e0; e < e1; e += 4) {
        int4 s4 = *(const int4*)&g_csrc[e];
        uint4 v0 = ld_row(z, s4.x, lane);
        uint4 v1 = ld_row(z, s4.y, lane);
        uint4 v2 = ld_row(z, s4.z, lane);
        uint4 v3 = ld_row(z, s4.w, lane);
        h8_add(v0, a); h8_add(v1, a); h8_add(v2, a); h8_add(v3, a);
    }
    float d = g_dinv[node];
    if (LAST) {
        float c = 0.9f * d;
        const float4* h0p = (const float4*)g_h0;
        float4 ha = h0p[(size_t)node * 32 + lane * 2];
        float4 hb = h0p[(size_t)node * 32 + lane * 2 + 1];
        outf[(size_t)node * 32 + lane * 2] =
            make_float4(c * a[0] + 0.1f * ha.x, c * a[1] + 0.1f * ha.y,
                        c * a[2] + 0.1f * ha.z, c * a[3] + 0.1f * ha.w);
        outf[(size_t)node * 32 + lane * 2 + 1] =
            make_float4(c * a[4] + 0.1f * hb.x, c * a[5] + 0.1f * hb.y,
                        c * a[6] + 0.1f * hb.z, c * a[7] + 0.1f * hb.w);
    } else {
        float c1 = 0.9f * d * d;
        uint4 hqv = ((const uint4*)g_hq)[(size_t)node * 16 + lane];
        const __half2* hh = (const __half2*)&hqv;
        float r[8];
#pragma unroll
        for (int j = 0; j < 4; j++) {
            float2 f = __half22float2(hh[j]);
            r[2 * j]     = c1 * a[2 * j]     + f.x;
            r[2 * j + 1] = c1 * a[2 * j + 1] + f.y;
        }
        zn[(size_t)node * 16 + lane] = pack8(r);
    }
}

// ------------------------- host orchestration -------------------------
extern "C" void kernel_launch(void* const* d_in, const int* in_sizes, int n_in,
                              void* d_out, int out_size) {
    const float* x_gene  = (const float*)d_in[0];
    const float* x_path  = (const float*)d_in[1];
    const float* x_vacc  = (const float*)d_in[2];
    const float* win_g   = (const float*)d_in[3];
    const float* bin_g   = (const float*)d_in[4];
    const float* win_p   = (const float*)d_in[5];
    const float* bin_p   = (const float*)d_in[6];
    const float* win_v   = (const float*)d_in[7];
    const float* bin_v   = (const float*)d_in[8];
    const float* wsl     = (const float*)d_in[9];
    const float* bsl     = (const float*)d_in[10];
    const float* wsr     = (const float*)d_in[11];
    const int*   ei_t    = (const int*)d_in[12];
    const int*   ei_in   = (const int*)d_in[13];
    const int*   ei_ct   = (const int*)d_in[14];
    const int*   ei_ii   = (const int*)d_in[15];
    float* out = (float*)d_out;

    float *h0, *bg, *dinv;
    __half *h16, *z16a, *z16b, *hq, *sg16, *sp16, *wtin16, *wtg16, *wtp16;
    int *cnts, *curz;
    cudaGetSymbolAddress((void**)&h0, g_h0);
    cudaGetSymbolAddress((void**)&h16, g_h16);
    cudaGetSymbolAddress((void**)&z16a, g_z16a);
    cudaGetSymbolAddress((void**)&z16b, g_z16b);
    cudaGetSymbolAddress((void**)&hq, g_hq);
    cudaGetSymbolAddress((void**)&sg16, g_sg16);
    cudaGetSymbolAddress((void**)&sp16, g_sp16);
    cudaGetSymbolAddress((void**)&wtin16, g_wtin16);
    cudaGetSymbolAddress((void**)&wtg16, g_wtg16);
    cudaGetSymbolAddress((void**)&wtp16, g_wtp16);
    cudaGetSymbolAddress((void**)&bg,  g_bg);
    cudaGetSymbolAddress((void**)&dinv, g_dinv);
    cudaGetSymbolAddress((void**)&cnts, g_cnts);
    cudaGetSymbolAddress((void**)&curz, g_curz);

    float* hg = h0;
    float* hp = h0 + (size_t)NG * HID;
    float* hv = h0 + (size_t)(NG + NP) * HID;
    __half* hg16 = h16;
    __half* hp16 = h16 + (size_t)NG * HID;
    __half* hv16 = h16 + (size_t)(NG + NP) * HID;

    const int TB = 256;
    static bool inited = false;
    static cudaStream_t ss;
    static cudaEvent_t evFork, evSetup, evPrep, evNPproj, evVac, evGB0, evGA0,
                       evGeneL0, evNP0, evGB1, evGA1, evP1, evNP1;
    if (!inited) {
        cudaFuncSetAttribute(k_gemm16<false, false>, cudaFuncAttributeMaxDynamicSharedMemorySize, GSMEM_BYTES);
        cudaFuncSetAttribute(k_gemm16<true,  true>,  cudaFuncAttributeMaxDynamicSharedMemorySize, GSMEM_BYTES);
        cudaStreamCreateWithFlags(&ss, cudaStreamNonBlocking);
        cudaEvent_t* evs[13] = {&evFork, &evSetup, &evPrep, &evNPproj, &evVac, &evGB0,
                                &evGA0, &evGeneL0, &evNP0, &evGB1, &evGA1, &evP1, &evNP1};
        for (int i = 0; i < 13; i++)
            cudaEventCreateWithFlags(evs[i], cudaEventDisableTiming);
        inited = true;
    }

    // ---------- fork: CSR setup on side stream ----------
    cudaEventRecord(evFork, 0);
    cudaStreamWaitEvent(ss, evFork, 0);
    cudaMemsetAsync(cnts, 0, CNTS_SZ * sizeof(int), ss);
    cudaMemsetAsync(curz, 0, CURZ_SZ * sizeof(int), ss);
    cudaMemsetAsync(h16 + (size_t)NT * HID,  0, HID * sizeof(__half), ss);
    cudaMemsetAsync(z16a + (size_t)NT * HID, 0, HID * sizeof(__half), ss);
    cudaMemsetAsync(z16b + (size_t)NT * HID, 0, HID * sizeof(__half), ss);
    k_hist4<<<CDIV(4 * EPER, TB), TB, 0, ss>>>(ei_t, ei_in, ei_ct, ei_ii);
    k_deg<<<CDIV(NT, TB), TB, 0, ss>>>();
    k_scan5<<<5, 1024, 0, ss>>>();
    k_scatter_all<<<CDIV(4 * EPER + NT, TB), TB, 0, ss>>>(ei_t, ei_in, ei_ct, ei_ii);
    k_padfill<<<CDIV(3 * NG + NP + NT, TB), TB, 0, ss>>>();
    cudaEventRecord(evSetup, ss);

    // ---------- main: weight prep then gene projection ----------
    const int PREP_N = (256 + 128 + 64) * 128 + 512 * 128 + 256 * 128;
    k_prep16<<<CDIV(PREP_N, TB), TB>>>(win_g, win_p, win_v, wsl, wsr, bsl, 0, 1);
    cudaEventRecord(evPrep, 0);
    k_gemm16<false, false><<<CDIV(NG, 128), 256, GSMEM_BYTES>>>(
        x_gene, wtin16, bin_g, (const float*)0, hg, hg16,
        (__half*)0, (__half*)0, (const float*)0, NG, 256, 1.f);

    // side: pathway projection
    cudaStreamWaitEvent(ss, evPrep, 0);
    k_gemm16<false, false><<<CDIV(NP, 128), 256, GSMEM_BYTES, ss>>>(
        x_path, wtin16 + 256 * 128, bin_p, (const float*)0, hp, hp16,
        (__half*)0, (__half*)0, (const float*)0, NP, 128, 1.f);
    cudaEventRecord(evNPproj, ss);

    // main: vaccine projection (needs dinv)
    cudaStreamWaitEvent(0, evSetup, 0);
    k_gemm16<false, false><<<CDIV(NV, 128), 256, GSMEM_BYTES>>>(
        x_vacc, wtin16 + (256 + 128) * 128, bin_v, (const float*)0, hv, hv16,
        z16a + (size_t)(NG + NP) * HID, hq + (size_t)(NG + NP) * HID,
        dinv + (NG + NP), NV, 64, 1.f);
    cudaEventRecord(evVac, 0);

    const int GA = CDIV((NG + NP) * 16, TB);
    const int GB_full = CDIV(2 * NG * 16, TB);
    const int GB_ct   = CDIV(NG * 16, TB);

    // ---------- SAGE layer 0 ----------
    cudaStreamWaitEvent(ss, evVac, 0);
    k_gather_B<<<GB_full, TB, 0, ss>>>(1);
    cudaEventRecord(evGB0, ss);
    cudaStreamWaitEvent(0, evNPproj, 0);
    k_gather_A<<<GA, TB>>>();
    cudaEventRecord(evGA0, 0);
    cudaStreamWaitEvent(0, evGB0, 0);
    k_gemm16<true, true><<<CDIV(NG, 128), 256, GSMEM_BYTES>>>(
        sg16, wtg16, bg, hg, hg, hg16, (__half*)0, (__half*)0, (const float*)0, NG, 512, 1.f / 3.f);
    cudaEventRecord(evGeneL0, 0);

    cudaStreamWaitEvent(ss, evGA0, 0);
    k_gemm16<true, true><<<CDIV(NP, 128), 256, GSMEM_BYTES, ss>>>(
        sp16, wtp16, bsl + 1 * 128, hp, hp, hp16, (__half*)0, (__half*)0, (const float*)0, NP, 256, 1.f);
    cudaEventRecord(evNP0, ss);
    k_gather_B<<<GB_ct, TB, 0, ss>>>(0);
    cudaEventRecord(evGB1, ss);
    cudaStreamWaitEvent(ss, evGeneL0, 0);
    k_prep16<<<CDIV(512 * 128 + 256 * 128, TB), TB, 0, ss>>>(win_g, win_p, win_v, wsl, wsr, bsl, 1, 0);
    cudaEventRecord(evP1, ss);

    // ---------- SAGE layer 1 ----------
    cudaStreamWaitEvent(0, evNP0, 0);
    k_gather_A<<<GA, TB>>>();
    cudaEventRecord(evGA1, 0);
    cudaStreamWaitEvent(0, evP1, 0);
    cudaStreamWaitEvent(0, evGB1, 0);
    k_gemm16<true, true><<<CDIV(NG, 128), 256, GSMEM_BYTES>>>(
        sg16, wtg16, bg, hg, hg, hg16, z16a, hq, dinv, NG, 512, 1.f / 3.f);

    cudaStreamWaitEvent(ss, evGA1, 0);
    k_gemm16<true, true><<<CDIV(NP, 128), 256, GSMEM_BYTES, ss>>>(
        sp16, wtp16, bsl + (4 + 1) * 128, hp, hp, hp16,
        z16a + (size_t)NG * HID, hq + (size_t)NG * HID, dinv + NG, NP, 256, 1.f);
    cudaEventRecord(evNP1, ss);

    // ---------- 8 APPNP iterations; last writes fp32 d_out ----------
    cudaStreamWaitEvent(0, evNP1, 0);
    const int AB = CDIV(NT * 16, TB);
    __half* bufs[2] = {z16a, z16b};
    for (int k = 0; k < 7; k++) {
        const __half* zin = bufs[k & 1];
        __half* zout = bufs[(k & 1) ^ 1];
        k_appnp_s<false><<<AB, TB>>>((const uint4*)zin, (uint4*)zout, (float4*)0);
    }
    k_appnp_s<true><<<AB, TB>>>((const uint4*)bufs[1], (uint4*)0, (float4*)out);
}

// round 16
// speedup vs baseline: 1.0121x; 1.0121x over previous
#include <cuda_runtime.h>
#include <cuda_fp16.h>
#include <cstdint>

#define NG 50000
#define NP 20000
#define NV 10000
#define NT 80000
#define HID 128
#define EPER 250000
#define CDIV(a,b) (((a)+(b)-1)/(b))

#define OFF_TG 0
#define OFF_IN (NG)
#define OFF_CT (NG+NP)
#define OFF_II (2*NG+NP)
#define CNTS_SZ (3*NG+NP)
#define CURZ_SZ (3*NG+NP+NT)

#define RB0 0
#define RB1 (EPER + 3*NG)
#define RB2 (RB1 + EPER + 3*NP)
#define RB3 (RB2 + EPER + 3*NG)
#define RSRC_SZ (RB3 + EPER + 3*NG)
#define CSRC_SZ (4*EPER + 4*NT)

// ------------------------- device scratch -------------------------
__device__ float g_h0[NT*HID];
__device__ __align__(16) __half g_h16[(NT+1)*HID];
__device__ __align__(16) __half g_z16a[(NT+1)*HID];
__device__ __align__(16) __half g_z16b[(NT+1)*HID];
__device__ __align__(16) __half g_hq[NT*HID];
__device__ __align__(16) __half g_sg16[NG*384];      // gene staging: [tg|ct|ii] only
__device__ __align__(16) __half g_sp16[NP*128];      // pathway staging: [in] only
__device__ __align__(16) __half g_wtin16[(256+128+64)*HID];
__device__ __align__(16) __half g_wtg16[512*HID];
__device__ __align__(16) __half g_wtp16[256*HID];
__device__ float g_bg[HID];
__device__ int   g_degi[NT];
__device__ float g_dinv[NT];
__device__ int   g_off[NT+1];
__device__ int   g_cnts[CNTS_SZ];
__device__ int   g_curz[CURZ_SZ];
__device__ __align__(16) int g_csrc[CSRC_SZ];
__device__ int   g_roff_tg[NG+1];
__device__ int   g_roff_in[NP+1];
__device__ int   g_roff_ct[NG+1];
__device__ int   g_roff_ii[NG+1];
__device__ __align__(16) int g_rsrc[RSRC_SZ];

__device__ __forceinline__ uint32_t h2u(__half2 h) {
    uint32_t u;
    memcpy(&u, &h, 4);
    return u;
}

// ------------------------- setup kernels -------------------------
__global__ void k_hist4(const int* __restrict__ e0, const int* __restrict__ e1,
                        const int* __restrict__ e2, const int* __restrict__ e3) {
    int t = blockIdx.x * blockDim.x + threadIdx.x;
    if (t >= 4 * EPER) return;
    int r = t / EPER, e = t - r * EPER;
    const int* ei = (r == 0) ? e0 : (r == 1) ? e1 : (r == 2) ? e2 : e3;
    int base = (r == 0) ? OFF_TG : (r == 1) ? OFF_IN : (r == 2) ? OFF_CT : OFF_II;
    atomicAdd(&g_cnts[base + ei[EPER + e]], 1);
}

__global__ void k_deg() {
    int i = blockIdx.x * blockDim.x + threadIdx.x;
    if (i >= NT) return;
    int d = 1;
    if (i < NG) d += g_cnts[OFF_TG + i] + g_cnts[OFF_CT + i] + g_cnts[OFF_II + i];
    else if (i < NG + NP) d += g_cnts[OFF_IN + (i - NG)];
    g_degi[i] = d;
    g_dinv[i] = rsqrtf((float)d);
}

__global__ void k_scan5() {
    __shared__ int part[1024];
    const int* cnt; int* off; int n;
    switch (blockIdx.x) {
        case 0: cnt = g_cnts + OFF_TG; off = g_roff_tg; n = NG; break;
        case 1: cnt = g_cnts + OFF_IN; off = g_roff_in; n = NP; break;
        case 2: cnt = g_cnts + OFF_CT; off = g_roff_ct; n = NG; break;
        case 3: cnt = g_cnts + OFF_II; off = g_roff_ii; n = NG; break;
        default: cnt = g_degi; off = g_off; n = NT; break;
    }
    int t = threadIdx.x;
    int chunk = (n + 1023) / 1024;
    int lo = t * chunk, hi = min(lo + chunk, n);
    int s = 0;
    for (int i = lo; i < hi; i++) s += (cnt[i] + 3) & ~3;
    part[t] = s;
    __syncthreads();
    for (int o = 1; o < 1024; o <<= 1) {
        int x = (t >= o) ? part[t - o] : 0;
        __syncthreads();
        part[t] += x;
        __syncthreads();
    }
    int run = part[t] - s;
    for (int i = lo; i < hi; i++) { off[i] = run; run += (cnt[i] + 3) & ~3; }
    if (t == 1023) off[n] = part[1023];
}

__global__ void k_scatter_all(const int* __restrict__ e0, const int* __restrict__ e1,
                              const int* __restrict__ e2, const int* __restrict__ e3) {
    int t = blockIdx.x * blockDim.x + threadIdx.x;
    if (t < 4 * EPER) {
        int r = t / EPER, e = t - r * EPER;
        const int* ei; const int* roff; int cbase, osrc, odst, rb;
        if (r == 0)      { ei = e0; roff = g_roff_tg; cbase = OFF_TG; osrc = NG + NP; odst = 0;  rb = RB0; }
        else if (r == 1) { ei = e1; roff = g_roff_in; cbase = OFF_IN; osrc = 0;       odst = NG; rb = RB1; }
        else if (r == 2) { ei = e2; roff = g_roff_ct; cbase = OFF_CT; osrc = NG;      odst = 0;  rb = RB2; }
        else             { ei = e3; roff = g_roff_ii; cbase = OFF_II; osrc = 0;       odst = 0;  rb = RB3; }
        int s = ei[e], d = ei[EPER + e];
        int gs = s + osrc;
        int p = roff[d] + atomicAdd(&g_curz[cbase + d], 1);
        g_rsrc[rb + p] = gs;
        int gd = d + odst;
        int p2 = g_off[gd] + atomicAdd(&g_curz[CNTS_SZ + gd], 1);
        g_csrc[p2] = gs;
    } else if (t < 4 * EPER + NT) {
        int i = t - 4 * EPER;
        int p = g_off[i] + atomicAdd(&g_curz[CNTS_SZ + i], 1);
        g_csrc[p] = i;
    }
}

__global__ void k_padfill() {
    int i = blockIdx.x * blockDim.x + threadIdx.x;
    if (i >= 3 * NG + NP + NT) return;
    const int* offp; int node, real; int* arr; int rb;
    if (i < NG)               { node = i;                 offp = g_roff_tg; real = g_cnts[OFF_TG + node]; arr = g_rsrc; rb = RB0; }
    else if (i < NG + NP)     { node = i - NG;            offp = g_roff_in; real = g_cnts[OFF_IN + node]; arr = g_rsrc; rb = RB1; }
    else if (i < 2 * NG + NP) { node = i - (NG + NP);     offp = g_roff_ct; real = g_cnts[OFF_CT + node]; arr = g_rsrc; rb = RB2; }
    else if (i < 3 * NG + NP) { node = i - (2 * NG + NP); offp = g_roff_ii; real = g_cnts[OFF_II + node]; arr = g_rsrc; rb = RB3; }
    else                      { node = i - (3 * NG + NP); offp = g_off;     real = g_degi[node];          arr = g_csrc; rb = 0;   }
    int o = rb + offp[node];
    int pad = (real + 3) & ~3;
    for (int j = real; j < pad; j++) arr[o + j] = NT;
}

__global__ void k_prep16(const float* __restrict__ wg, const float* __restrict__ wp,
                         const float* __restrict__ wv, const float* __restrict__ wsl,
                         const float* __restrict__ wsr, const float* __restrict__ bsl,
                         int l, int do_in) {
    int idx = blockIdx.x * blockDim.x + threadIdx.x;
    const int TIN = (256 + 128 + 64) * 128;
    const int WG  = 512 * 128;
    int base = do_in ? TIN : 0;
    if (do_in && idx < TIN) {
        float v;
        if (idx < 256 * 128) v = wg[idx];
        else if (idx < (256 + 128) * 128) v = wp[idx - 256 * 128];
        else v = wv[idx - (256 + 128) * 128];
        g_wtin16[idx] = __float2half(v);
        return;
    }
    int i = idx - base;
    if (i < 0) return;
    if (i < WG) {
        int n = i >> 9, k = i & 511;
        int b = k >> 7, kk = k & 127;
        float v;
        if (b == 0)      v = wsl[((l * 4 + 0) * 128 + n) * 128 + kk];
        else if (b == 1) v = wsl[((l * 4 + 2) * 128 + n) * 128 + kk];
        else if (b == 2) v = wsl[((l * 4 + 3) * 128 + n) * 128 + kk];
        else             v = wsr[((l * 4 + 0) * 128 + n) * 128 + kk]
                           + wsr[((l * 4 + 2) * 128 + n) * 128 + kk]
                           + wsr[((l * 4 + 3) * 128 + n) * 128 + kk];
        g_wtg16[i] = __float2half(v);
        if (i < 128)
            g_bg[i] = bsl[(l * 4 + 0) * 128 + i] + bsl[(l * 4 + 2) * 128 + i]
                    + bsl[(l * 4 + 3) * 128 + i];
    } else if (i < WG + 256 * 128) {
        int j = i - WG;
        int n = j >> 8, k = j & 255;
        int b = k >> 7, kk = k & 127;
        float v = (b == 0) ? wsl[((l * 4 + 1) * 128 + n) * 128 + kk]
                           : wsr[((l * 4 + 1) * 128 + n) * 128 + kk];
        g_wtp16[j] = __float2half(v);
    }
}

// ------------------------- FP16 tensor-core GEMM (KTILE=32, split-A) -------------------------
__device__ __forceinline__ void mma_f16(float c[4], uint32_t a0, uint32_t a1,
                                        uint32_t a2, uint32_t a3,
                                        uint32_t b0, uint32_t b1) {
    asm volatile(
        "mma.sync.aligned.m16n8k16.row.col.f32.f16.f16.f32 "
        "{%0,%1,%2,%3}, {%4,%5,%6,%7}, {%8,%9}, {%0,%1,%2,%3};"
        : "+f"(c[0]), "+f"(c[1]), "+f"(c[2]), "+f"(c[3])
        : "r"(a0), "r"(a1), "r"(a2), "r"(a3), "r"(b0), "r"(b1));
}

#define SST 20
#define TBUF (128*SST)
#define GSMEM_BYTES (4*TBUF*4)

// A (k<split) from Araw [M, astride]; A (k>=split) from A2 [M, HID]. Non-AH: fp32 A, no split.
template<bool RES, bool AH>
__global__ __launch_bounds__(256)
void k_gemm16(const void* __restrict__ Araw, const __half* __restrict__ A2,
              int astride, int split,
              const __half* __restrict__ W16,
              const float* __restrict__ bias, const float* __restrict__ res,
              float* __restrict__ out, __half* __restrict__ h16out,
              __half* __restrict__ zs, __half* __restrict__ hqo,
              const float* __restrict__ dv,
              int M, int K, float scale)
{
    extern __shared__ uint32_t sm[];
    uint32_t* Asm = sm;
    uint32_t* Bsm = sm + 2 * TBUF;

    int tid  = threadIdx.x;
    int lane = tid & 31;
    int wid  = tid >> 5;
    int wm = wid >> 2;
    int wn = wid & 3;
    int g   = lane >> 2;
    int tig = lane & 3;

    int rowBase = blockIdx.x * 128;
    int r_ld  = tid >> 1;
    int hsel  = (tid & 1);

    float acc[4][4][4];
#pragma unroll
    for (int mt = 0; mt < 4; mt++)
#pragma unroll
        for (int nt = 0; nt < 4; nt++)
#pragma unroll
            for (int r = 0; r < 4; r++) acc[mt][nt][r] = 0.f;

    int ntk = K >> 5;
    int gr = rowBase + r_ld;
    const __half* Ah = (const __half*)Araw;
    const float*  Af = (const float*)Araw;

    auto loadA = [&](int k0, uint4& u0, uint4& u1) {
        if (AH) {
            if (gr < M) {
                int k = k0 + hsel * 16;
                const uint4* p = (k < split)
                    ? (const uint4*)&Ah[(size_t)gr * astride + k]
                    : (const uint4*)&A2[(size_t)gr * HID + (k - split)];
                u0 = p[0]; u1 = p[1];
            } else { u0 = make_uint4(0,0,0,0); u1 = make_uint4(0,0,0,0); }
        } else {
            if (gr < M) {
                const float4* p = (const float4*)&Af[(size_t)gr * K + k0 + hsel * 16];
                float4 f0 = p[0], f1 = p[1], f2 = p[2], f3 = p[3];
                uint32_t* w0 = (uint32_t*)&u0;
                uint32_t* w1 = (uint32_t*)&u1;
                w0[0] = h2u(__floats2half2_rn(f0.x, f0.y));
                w0[1] = h2u(__floats2half2_rn(f0.z, f0.w));
                w0[2] = h2u(__floats2half2_rn(f1.x, f1.y));
                w0[3] = h2u(__floats2half2_rn(f1.z, f1.w));
                w1[0] = h2u(__floats2half2_rn(f2.x, f2.y));
                w1[1] = h2u(__floats2half2_rn(f2.z, f2.w));
                w1[2] = h2u(__floats2half2_rn(f3.x, f3.y));
                w1[3] = h2u(__floats2half2_rn(f3.z, f3.w));
            } else { u0 = make_uint4(0,0,0,0); u1 = make_uint4(0,0,0,0); }
        }
    };
    auto loadB = [&](int k0, uint4& u0, uint4& u1) {
        const uint4* p = (const uint4*)&W16[(size_t)r_ld * K + k0 + hsel * 16];
        u0 = p[0]; u1 = p[1];
    };
    auto store = [&](uint32_t* buf, uint4 u0, uint4 u1) {
        int base = r_ld * SST + hsel * 8;
        *(uint4*)&buf[base] = u0;
        *(uint4*)&buf[base + 4] = u1;
    };

    {
        uint4 a0, a1, b0, b1;
        loadA(0, a0, a1);
        loadB(0, b0, b1);
        store(Asm, a0, a1);
        store(Bsm, b0, b1);
    }
    __syncthreads();

    for (int t = 0; t < ntk; t++) {
        int buf = t & 1;
        bool more = (t + 1 < ntk);
        uint4 an0, an1, bn0, bn1;
        if (more) {
            int k0 = (t + 1) << 5;
            loadA(k0, an0, an1);
            loadB(k0, bn0, bn1);
        }
        const uint32_t* Ab = Asm + buf * TBUF;
        const uint32_t* Bb = Bsm + buf * TBUF;
#pragma unroll
        for (int ks2 = 0; ks2 < 16; ks2 += 8) {
            uint32_t af[4][4], bf[4][2];
#pragma unroll
            for (int mt = 0; mt < 4; mt++) {
                int r0 = wm * 64 + mt * 16 + g;
                af[mt][0] = Ab[r0 * SST + ks2 + tig];
                af[mt][1] = Ab[(r0 + 8) * SST + ks2 + tig];
                af[mt][2] = Ab[r0 * SST + ks2 + tig + 4];
                af[mt][3] = Ab[(r0 + 8) * SST + ks2 + tig + 4];
            }
#pragma unroll
            for (int nt = 0; nt < 4; nt++) {
                int c0 = wn * 32 + nt * 8 + g;
                bf[nt][0] = Bb[c0 * SST + ks2 + tig];
                bf[nt][1] = Bb[c0 * SST + ks2 + tig + 4];
            }
#pragma unroll
            for (int mt = 0; mt < 4; mt++)
#pragma unroll
                for (int nt = 0; nt < 4; nt++)
                    mma_f16(acc[mt][nt], af[mt][0], af[mt][1], af[mt][2], af[mt][3],
                            bf[nt][0], bf[nt][1]);
        }
        if (more) {
            int nb = buf ^ 1;
            store(Asm + nb * TBUF, an0, an1);
            store(Bsm + nb * TBUF, bn0, bn1);
        }
        __syncthreads();
    }

#pragma unroll
    for (int mt = 0; mt < 4; mt++) {
#pragma unroll
        for (int nt = 0; nt < 4; nt++) {
            int col = wn * 32 + nt * 8 + tig * 2;
            float b0 = bias[col], b1 = bias[col + 1];
#pragma unroll
            for (int h = 0; h < 2; h++) {
                int row = rowBase + wm * 64 + mt * 16 + g + h * 8;
                if (row >= M) continue;
                float v0 = acc[mt][nt][h * 2 + 0] + b0;
                float v1 = acc[mt][nt][h * 2 + 1] + b1;
                if (RES) {
                    float2 rv = *(const float2*)&res[(size_t)row * HID + col];
                    v0 = rv.x + v0 * scale;
                    v1 = rv.y + v1 * scale;
                }
                v0 = fmaxf(v0, 0.f);
                v1 = fmaxf(v1, 0.f);
                float2 o; o.x = v0; o.y = v1;
                *(float2*)&out[(size_t)row * HID + col] = o;
                *(__half2*)&h16out[(size_t)row * HID + col] = __floats2half2_rn(v0, v1);
                if (zs) {
                    float d = dv[row];
                    *(__half2*)&zs[(size_t)row * HID + col] =
                        __floats2half2_rn(v0 * d, v1 * d);
                    *(__half2*)&hqo[(size_t)row * HID + col] =
                        __floats2half2_rn(0.1f * d * v0, 0.1f * d * v1);
                }
            }
        }
    }
}

// ------------------------- fp16 helpers -------------------------
__device__ __forceinline__ void h8_add(uint4 v, float a[8]) {
    const __half2* h = (const __half2*)&v;
#pragma unroll
    for (int j = 0; j < 4; j++) {
        float2 f = __half22float2(h[j]);
        a[2 * j]     += f.x;
        a[2 * j + 1] += f.y;
    }
}
__device__ __forceinline__ uint4 pack8(const float r[8]) {
    uint4 pk;
    __half2* ph = (__half2*)&pk;
    ph[0] = __floats2half2_rn(r[0], r[1]);
    ph[1] = __floats2half2_rn(r[2], r[3]);
    ph[2] = __floats2half2_rn(r[4], r[5]);
    ph[3] = __floats2half2_rn(r[6], r[7]);
    return pk;
}

// gather core: 16 lanes/node, padded CSR (pads hit zero row NT), mean into dst (fp16)
__device__ __forceinline__ void gather_node(int node, const int* offp, const int* es,
                                            int real, __half* dst, int strideH, int colH,
                                            int lane) {
    const uint4* x4 = (const uint4*)g_h16;
    int e0 = offp[node], e1 = offp[node + 1];
    float a[8] = {0.f, 0.f, 0.f, 0.f, 0.f, 0.f, 0.f, 0.f};
    for (int e = e0; e < e1; e += 4) {
        int4 s4 = *(const int4*)&es[e];
        uint4 v0 = __ldg(&x4[(size_t)s4.x * 16 + lane]);
        uint4 v1 = __ldg(&x4[(size_t)s4.y * 16 + lane]);
        uint4 v2 = __ldg(&x4[(size_t)s4.z * 16 + lane]);
        uint4 v3 = __ldg(&x4[(size_t)s4.w * 16 + lane]);
        h8_add(v0, a); h8_add(v1, a); h8_add(v2, a); h8_add(v3, a);
    }
    float inv = 1.f / fmaxf((float)real, 1.f);
    float r[8];
#pragma unroll
    for (int j = 0; j < 8; j++) r[j] = a[j] * inv;
    *(uint4*)&dst[(size_t)node * strideH + colH + lane * 8] = pack8(r);
}

// gather A: ii (sg col 256); in (sp col 0)
__global__ void k_gather_A() {
    int t = blockIdx.x * blockDim.x + threadIdx.x;
    int lane = t & 15, slot = t >> 4;
    if (slot >= NG + NP) return;
    if (slot < NG) {
        gather_node(slot, g_roff_ii, g_rsrc + RB3, g_cnts[OFF_II + slot],
                    g_sg16, 384, 256, lane);
    } else {
        int node = slot - NG;
        gather_node(node, g_roff_in, g_rsrc + RB1, g_cnts[OFF_IN + node],
                    g_sp16, 128, 0, lane);
    }
}

// gather B: optional tg (sg col 0) + ct (sg col 128)
__global__ void k_gather_B(int do_tg) {
    int t = blockIdx.x * blockDim.x + threadIdx.x;
    int lane = t & 15, slot = t >> 4;
    int n_slots = do_tg ? 2 * NG : NG;
    if (slot >= n_slots) return;
    if (do_tg && slot < NG) {
        gather_node(slot, g_roff_tg, g_rsrc + RB0, g_cnts[OFF_TG + slot],
                    g_sg16, 384, 0, lane);
    } else {
        int node = do_tg ? slot - NG : slot;
        gather_node(node, g_roff_ct, g_rsrc + RB2, g_cnts[OFF_CT + node],
                    g_sg16, 384, 128, lane);
    }
}

// ------------------------- APPNP step (padded CSR, 16 lanes/node) -------------------------
template<bool LAST>
__global__ void k_appnp_s(const uint4* __restrict__ z, uint4* __restrict__ zn,
                          float4* __restrict__ outf) {
    int t = blockIdx.x * blockDim.x + threadIdx.x;
    int lane = t & 15, node = t >> 4;
    if (node >= NT) return;
    int e0 = g_off[node], e1 = g_off[node + 1];
    float a[8] = {0.f, 0.f, 0.f, 0.f, 0.f, 0.f, 0.f, 0.f};
    for (int e = e0; e < e1; e += 4) {
        int4 s4 = *(const int4*)&g_csrc[e];
        uint4 v0 = __ldg(&z[(size_t)s4.x * 16 + lane]);
        uint4 v1 = __ldg(&z[(size_t)s4.y * 16 + lane]);
        uint4 v2 = __ldg(&z[(size_t)s4.z * 16 + lane]);
        uint4 v3 = __ldg(&z[(size_t)s4.w * 16 + lane]);
        h8_add(v0, a); h8_add(v1, a); h8_add(v2, a); h8_add(v3, a);
    }
    float d = g_dinv[node];
    if (LAST) {
        float c = 0.9f * d;
        const float4* h0p = (const float4*)g_h0;
        float4 ha = h0p[(size_t)node * 32 + lane * 2];
        float4 hb = h0p[(size_t)node * 32 + lane * 2 + 1];
        outf[(size_t)node * 32 + lane * 2] =
            make_float4(c * a[0] + 0.1f * ha.x, c * a[1] + 0.1f * ha.y,
                        c * a[2] + 0.1f * ha.z, c * a[3] + 0.1f * ha.w);
        outf[(size_t)node * 32 + lane * 2 + 1] =
            make_float4(c * a[4] + 0.1f * hb.x, c * a[5] + 0.1f * hb.y,
                        c * a[6] + 0.1f * hb.z, c * a[7] + 0.1f * hb.w);
    } else {
        float c1 = 0.9f * d * d;
        uint4 hqv = ((const uint4*)g_hq)[(size_t)node * 16 + lane];
        const __half2* hh = (const __half2*)&hqv;
        float r[8];
#pragma unroll
        for (int j = 0; j < 4; j++) {
            float2 f = __half22float2(hh[j]);
            r[2 * j]     = c1 * a[2 * j]     + f.x;
            r[2 * j + 1] = c1 * a[2 * j + 1] + f.y;
        }
        zn[(size_t)node * 16 + lane] = pack8(r);
    }
}

// ------------------------- host orchestration -------------------------
extern "C" void kernel_launch(void* const* d_in, const int* in_sizes, int n_in,
                              void* d_out, int out_size) {
    const float* x_gene  = (const float*)d_in[0];
    const float* x_path  = (const float*)d_in[1];
    const float* x_vacc  = (const float*)d_in[2];
    const float* win_g   = (const float*)d_in[3];
    const float* bin_g   = (const float*)d_in[4];
    const float* win_p   = (const float*)d_in[5];
    const float* bin_p   = (const float*)d_in[6];
    const float* win_v   = (const float*)d_in[7];
    const float* bin_v   = (const float*)d_in[8];
    const float* wsl     = (const float*)d_in[9];
    const float* bsl     = (const float*)d_in[10];
    const float* wsr     = (const float*)d_in[11];
    const int*   ei_t    = (const int*)d_in[12];
    const int*   ei_in   = (const int*)d_in[13];
    const int*   ei_ct   = (const int*)d_in[14];
    const int*   ei_ii   = (const int*)d_in[15];
    float* out = (float*)d_out;

    float *h0, *bg, *dinv;
    __half *h16, *z16a, *z16b, *hq, *sg16, *sp16, *wtin16, *wtg16, *wtp16;
    int *cnts, *curz;
    cudaGetSymbolAddress((void**)&h0, g_h0);
    cudaGetSymbolAddress((void**)&h16, g_h16);
    cudaGetSymbolAddress((void**)&z16a, g_z16a);
    cudaGetSymbolAddress((void**)&z16b, g_z16b);
    cudaGetSymbolAddress((void**)&hq, g_hq);
    cudaGetSymbolAddress((void**)&sg16, g_sg16);
    cudaGetSymbolAddress((void**)&sp16, g_sp16);
    cudaGetSymbolAddress((void**)&wtin16, g_wtin16);
    cudaGetSymbolAddress((void**)&wtg16, g_wtg16);
    cudaGetSymbolAddress((void**)&wtp16, g_wtp16);
    cudaGetSymbolAddress((void**)&bg,  g_bg);
    cudaGetSymbolAddress((void**)&dinv, g_dinv);
    cudaGetSymbolAddress((void**)&cnts, g_cnts);
    cudaGetSymbolAddress((void**)&curz, g_curz);

    float* hg = h0;
    float* hp = h0 + (size_t)NG * HID;
    float* hv = h0 + (size_t)(NG + NP) * HID;
    __half* hg16 = h16;
    __half* hp16 = h16 + (size_t)NG * HID;
    __half* hv16 = h16 + (size_t)(NG + NP) * HID;

    const int TB = 256;
    static bool inited = false;
    static cudaStream_t ss;
    static cudaEvent_t evFork, evSetup, evPrep, evNPproj, evVac, evGB0, evGA0,
                       evGeneL0, evNP0, evGB1, evGA1, evP1, evNP1;
    if (!inited) {
        cudaFuncSetAttribute(k_gemm16<false, false>, cudaFuncAttributeMaxDynamicSharedMemorySize, GSMEM_BYTES);
        cudaFuncSetAttribute(k_gemm16<true,  true>,  cudaFuncAttributeMaxDynamicSharedMemorySize, GSMEM_BYTES);
        cudaStreamCreateWithFlags(&ss, cudaStreamNonBlocking);
        cudaEvent_t* evs[13] = {&evFork, &evSetup, &evPrep, &evNPproj, &evVac, &evGB0,
                                &evGA0, &evGeneL0, &evNP0, &evGB1, &evGA1, &evP1, &evNP1};
        for (int i = 0; i < 13; i++)
            cudaEventCreateWithFlags(evs[i], cudaEventDisableTiming);
        inited = true;
    }

    // ---------- fork: CSR setup on side stream ----------
    cudaEventRecord(evFork, 0);
    cudaStreamWaitEvent(ss, evFork, 0);
    cudaMemsetAsync(cnts, 0, CNTS_SZ * sizeof(int), ss);
    cudaMemsetAsync(curz, 0, CURZ_SZ * sizeof(int), ss);
    cudaMemsetAsync(h16 + (size_t)NT * HID,  0, HID * sizeof(__half), ss);
    cudaMemsetAsync(z16a + (size_t)NT * HID, 0, HID * sizeof(__half), ss);
    cudaMemsetAsync(z16b + (size_t)NT * HID, 0, HID * sizeof(__half), ss);
    k_hist4<<<CDIV(4 * EPER, TB), TB, 0, ss>>>(ei_t, ei_in, ei_ct, ei_ii);
    k_deg<<<CDIV(NT, TB), TB, 0, ss>>>();
    k_scan5<<<5, 1024, 0, ss>>>();
    k_scatter_all<<<CDIV(4 * EPER + NT, TB), TB, 0, ss>>>(ei_t, ei_in, ei_ct, ei_ii);
    k_padfill<<<CDIV(3 * NG + NP + NT, TB), TB, 0, ss>>>();
    cudaEventRecord(evSetup, ss);

    // ---------- main: weight prep then gene projection ----------
    const int PREP_N = (256 + 128 + 64) * 128 + 512 * 128 + 256 * 128;
    k_prep16<<<CDIV(PREP_N, TB), TB>>>(win_g, win_p, win_v, wsl, wsr, bsl, 0, 1);
    cudaEventRecord(evPrep, 0);
    k_gemm16<false, false><<<CDIV(NG, 128), 256, GSMEM_BYTES>>>(
        x_gene, (const __half*)0, 256, 256, wtin16, bin_g, (const float*)0, hg, hg16,
        (__half*)0, (__half*)0, (const float*)0, NG, 256, 1.f);

    // side: pathway projection
    cudaStreamWaitEvent(ss, evPrep, 0);
    k_gemm16<false, false><<<CDIV(NP, 128), 256, GSMEM_BYTES, ss>>>(
        x_path, (const __half*)0, 128, 128, wtin16 + 256 * 128, bin_p, (const float*)0, hp, hp16,
        (__half*)0, (__half*)0, (const float*)0, NP, 128, 1.f);
    cudaEventRecord(evNPproj, ss);

    // main: vaccine projection (needs dinv)
    cudaStreamWaitEvent(0, evSetup, 0);
    k_gemm16<false, false><<<CDIV(NV, 128), 256, GSMEM_BYTES>>>(
        x_vacc, (const __half*)0, 64, 64, wtin16 + (256 + 128) * 128, bin_v, (const float*)0, hv, hv16,
        z16a + (size_t)(NG + NP) * HID, hq + (size_t)(NG + NP) * HID,
        dinv + (NG + NP), NV, 64, 1.f);
    cudaEventRecord(evVac, 0);

    const int GA = CDIV((NG + NP) * 16, TB);
    const int GB_full = CDIV(2 * NG * 16, TB);
    const int GB_ct   = CDIV(NG * 16, TB);

    // ---------- SAGE layer 0 ----------
    cudaStreamWaitEvent(ss, evVac, 0);
    k_gather_B<<<GB_full, TB, 0, ss>>>(1);
    cudaEventRecord(evGB0, ss);
    cudaStreamWaitEvent(0, evNPproj, 0);
    k_gather_A<<<GA, TB>>>();
    cudaEventRecord(evGA0, 0);
    cudaStreamWaitEvent(0, evGB0, 0);
    k_gemm16<true, true><<<CDIV(NG, 128), 256, GSMEM_BYTES>>>(
        sg16, hg16, 384, 384, wtg16, bg, hg, hg, hg16,
        (__half*)0, (__half*)0, (const float*)0, NG, 512, 1.f / 3.f);
    cudaEventRecord(evGeneL0, 0);

    cudaStreamWaitEvent(ss, evGA0, 0);
    k_gemm16<true, true><<<CDIV(NP, 128), 256, GSMEM_BYTES, ss>>>(
        sp16, hp16, 128, 128, wtp16, bsl + 1 * 128, hp, hp, hp16,
        (__half*)0, (__half*)0, (const float*)0, NP, 256, 1.f);
    cudaEventRecord(evNP0, ss);
    k_gather_B<<<GB_ct, TB, 0, ss>>>(0);
    cudaEventRecord(evGB1, ss);
    cudaStreamWaitEvent(ss, evGeneL0, 0);
    k_prep16<<<CDIV(512 * 128 + 256 * 128, TB), TB, 0, ss>>>(win_g, win_p, win_v, wsl, wsr, bsl, 1, 0);
    cudaEventRecord(evP1, ss);

    // ---------- SAGE layer 1 ----------
    cudaStreamWaitEvent(0, evNP0, 0);
    k_gather_A<<<GA, TB>>>();
    cudaEventRecord(evGA1, 0);
    cudaStreamWaitEvent(0, evP1, 0);
    cudaStreamWaitEvent(0, evGB1, 0);
    k_gemm16<true, true><<<CDIV(NG, 128), 256, GSMEM_BYTES>>>(
        sg16, hg16, 384, 384, wtg16, bg, hg, hg, hg16, z16a, hq, dinv, NG, 512, 1.f / 3.f);

    cudaStreamWaitEvent(ss, evGA1, 0);
    k_gemm16<true, true><<<CDIV(NP, 128), 256, GSMEM_BYTES, ss>>>(
        sp16, hp16, 128, 128, wtp16, bsl + (4 + 1) * 128, hp, hp, hp16,
        z16a + (size_t)NG * HID, hq + (size_t)NG * HID, dinv + NG, NP, 256, 1.f);
    cudaEventRecord(evNP1, ss);

    // ---------- 8 APPNP iterations; last writes fp32 d_out ----------
    cudaStreamWaitEvent(0, evNP1, 0);
    const int AB = CDIV(NT * 16, TB);
    __half* bufs[2] = {z16a, z16b};
    for (int k = 0; k < 7; k++) {
        const __half* zin = bufs[k & 1];
        __half* zout = bufs[(k & 1) ^ 1];
        k_appnp_s<false><<<AB, TB>>>((const uint4*)zin, (uint4*)zout, (float4*)0);
    }
    k_appnp_s<true><<<AB, TB>>>((const uint4*)bufs[1], (uint4*)0, (float4*)out);
}